// round 7
// baseline (speedup 1.0000x reference)
#include <cuda_runtime.h>
#include <math.h>
#include <stdint.h>

#define BATCH 8
#define CIN   128
#define H     112
#define W     112
#define COUT  256
#define OFFC  18
#define HW    (H * W)
#define KCH   36        // k chunks of 32 (1152 total)

// ---------------------------------------------------------------------------
// Scratch (allocation-free rule: __device__ globals)
// ---------------------------------------------------------------------------
__device__ float g_offset[BATCH * OFFC * HW];
__device__ __align__(16) float g_xt[(size_t)BATCH * HW * CIN];   // (B,H,W,C)
__device__ __align__(16) float g_st[(size_t)BATCH * HW * CIN];   // sampled, (B,H,W,C)
// tf32 weights: [cog(2)][chunk(36)][m(128)][k(32)]
__device__ __align__(16) unsigned int g_wpre[2 * KCH * 4096];

// ---------------------------------------------------------------------------
// helpers
// ---------------------------------------------------------------------------
__device__ __forceinline__ uint32_t smem_u32(const void* p) {
    uint32_t a;
    asm("{ .reg .u64 t; cvta.to.shared.u64 t, %1; cvt.u32.u64 %0, t; }" : "=r"(a) : "l"(p));
    return a;
}
__device__ __forceinline__ unsigned int to_tf32(float v) {
    unsigned int t; asm("cvt.rna.tf32.f32 %0, %1;" : "=r"(t) : "f"(v)); return t;
}
__device__ __forceinline__ void cp16(uint32_t dst, const void* src) {
    asm volatile("cp.async.cg.shared.global [%0], [%1], 16;" :: "r"(dst), "l"(src) : "memory");
}
#define CP_COMMIT() asm volatile("cp.async.commit_group;" ::: "memory")
#define CP_WAIT0()  asm volatile("cp.async.wait_group 0;" ::: "memory")

__device__ __forceinline__ void mma_tf32(float* d, const unsigned* a, const unsigned* b) {
    asm volatile(
        "mma.sync.aligned.m16n8k8.row.col.f32.tf32.tf32.f32 "
        "{%0,%1,%2,%3}, {%4,%5,%6,%7}, {%8,%9}, {%0,%1,%2,%3};"
        : "+f"(d[0]), "+f"(d[1]), "+f"(d[2]), "+f"(d[3])
        : "r"(a[0]), "r"(a[1]), "r"(a[2]), "r"(a[3]), "r"(b[0]), "r"(b[1]));
}

// ---------------------------------------------------------------------------
// Kernel 0: transpose x (B,C,H,W) -> g_xt (B,H,W,C)
// ---------------------------------------------------------------------------
__global__ void transpose_kernel(const float* __restrict__ x) {
    __shared__ float tile[CIN * 29];
    const int h = blockIdx.x;
    const int b = blockIdx.y;
    const int tid = threadIdx.x;
    for (int wc = 0; wc < 4; wc++) {
        for (int e = tid; e < CIN * 28; e += 256) {
            int c = e / 28, j = e % 28;
            tile[c * 29 + j] = x[((size_t)(b * CIN + c) * H + h) * W + wc * 28 + j];
        }
        __syncthreads();
        for (int e = tid; e < CIN * 28; e += 256) {
            int j = e >> 7, c = e & 127;
            g_xt[(((size_t)b * H + h) * W + wc * 28 + j) * CIN + c] = tile[c * 29 + j];
        }
        __syncthreads();
    }
}

// ---------------------------------------------------------------------------
// Kernel 1: offset conv — 2 h-rows per block (weight LDS amortized x2)
// ---------------------------------------------------------------------------
#define K1_CK 16
__global__ void offset_conv_kernel(const float* __restrict__ x,
                                   const float* __restrict__ ow,
                                   const float* __restrict__ ob) {
    __shared__ float sW[K1_CK * 9 * OFFC];
    __shared__ float sX[K1_CK * 4 * 114];     // rows h0-1 .. h0+2
    const int h0 = blockIdx.x * 2;
    const int b  = blockIdx.y;
    const int tid = threadIdx.x;
    const int w = tid;

    float acc0[OFFC], acc1[OFFC];
#pragma unroll
    for (int oc = 0; oc < OFFC; oc++) { acc0[oc] = ob[oc]; acc1[oc] = acc0[oc]; }

    for (int c0 = 0; c0 < CIN; c0 += K1_CK) {
        for (int e = tid; e < K1_CK * 4 * 114; e += blockDim.x) {
            int ci = e / (4 * 114), rem = e % (4 * 114);
            int r = rem / 114, j = rem % 114;
            int row = h0 - 1 + r, col = j - 1;
            float v = 0.f;
            if (row >= 0 && row < H && col >= 0 && col < W)
                v = x[((size_t)(b * CIN + c0 + ci) * H + row) * W + col];
            sX[e] = v;
        }
        for (int e = tid; e < K1_CK * 9 * OFFC; e += blockDim.x) {
            int ci = e / (9 * OFFC), rem = e % (9 * OFFC);
            int k = rem / OFFC, oc = rem % OFFC;
            sW[e] = ow[(oc * CIN + c0 + ci) * 9 + k];
        }
        __syncthreads();
        if (w < W) {
            for (int ci = 0; ci < K1_CK; ci++) {
                float xv[4][3];
#pragma unroll
                for (int r = 0; r < 4; r++)
#pragma unroll
                    for (int kx = 0; kx < 3; kx++)
                        xv[r][kx] = sX[(ci * 4 + r) * 114 + w + kx];
#pragma unroll
                for (int k = 0; k < 9; k++) {
                    int ky = k / 3, kx = k % 3;
                    float v0 = xv[ky][kx];
                    float v1 = xv[ky + 1][kx];
                    const float* wp = &sW[(ci * 9 + k) * OFFC];
#pragma unroll
                    for (int oc = 0; oc < OFFC; oc++) {
                        float wv = wp[oc];
                        acc0[oc] += v0 * wv;
                        acc1[oc] += v1 * wv;
                    }
                }
            }
        }
        __syncthreads();
    }
    if (w < W) {
#pragma unroll
        for (int oc = 0; oc < OFFC; oc++) {
            g_offset[((size_t)(b * OFFC + oc) * H + h0)     * W + w] = acc0[oc];
            g_offset[((size_t)(b * OFFC + oc) * H + h0 + 1) * W + w] = acc1[oc];
        }
    }
}

// ---------------------------------------------------------------------------
// Kernel 2: sampling v2 — corner table in smem, channel-vectorized gathers
// from g_xt (NHWC). Block = (b,h) row, 128 threads (4 warps).
// ---------------------------------------------------------------------------
__global__ void __launch_bounds__(128) sample_kernel() {
    __shared__ float2 sTab[112 * 36];     // {idx-as-float, weight}
    const int h = blockIdx.x;
    const int b = blockIdx.y;
    const int tid = threadIdx.x;
    const int wid = tid >> 5;
    const int lane = tid & 31;

    // phase 1: per-pixel corner tables
    if (tid < W) {
        const int w = tid;
        const float* offp = g_offset + (size_t)b * OFFC * HW + h * W + w;
#pragma unroll
        for (int p = 0; p < 9; p++) {
            int ky = p / 3, kx = p % 3;
            float offY = offp[(size_t)p * HW];
            float offX = offp[(size_t)(9 + p) * HW];
            float sy = (float)(h + ky - 1) + offY;
            float sx = (float)(w + kx - 1) + offX;
            float fy0 = floorf(sy), fx0 = floorf(sx);
            int y0 = (int)fy0, x0 = (int)fx0;
            float wy = sy - fy0, wx = sx - fx0;
#pragma unroll
            for (int q = 0; q < 4; q++) {
                int yi = y0 + (q >> 1), xi = x0 + (q & 1);
                float wgt = ((q >> 1) ? wy : 1.f - wy) * ((q & 1) ? wx : 1.f - wx);
                bool valid = (yi >= 0) & (yi < H) & (xi >= 0) & (xi < W);
                int yc = min(max(yi, 0), H - 1);
                int xc = min(max(xi, 0), W - 1);
                sTab[w * 36 + p * 4 + q] =
                    make_float2(__int_as_float(yc * W + xc), valid ? wgt : 0.f);
            }
        }
    }
    __syncthreads();

    // phase 2: warp per pixel, lane = 4 channels
    const float* xtb = g_xt + (size_t)b * HW * CIN;
    float* stb = g_st + (size_t)b * HW * CIN;
    for (int w = wid; w < W; w += 4) {
        float4 acc = make_float4(0.f, 0.f, 0.f, 0.f);
        const float2* tab = &sTab[w * 36];
#pragma unroll 9
        for (int q = 0; q < 36; q++) {
            float2 t = tab[q];
            int pix = __float_as_int(t.x);
            float wt = t.y;
            float4 v = *reinterpret_cast<const float4*>(xtb + (size_t)pix * CIN + lane * 4);
            acc.x += wt * v.x; acc.y += wt * v.y;
            acc.z += wt * v.z; acc.w += wt * v.w;
        }
        *reinterpret_cast<float4*>(stb + (size_t)(h * W + w) * CIN + lane * 4) = acc;
    }
}

// ---------------------------------------------------------------------------
// Kernel 2.5: weight prep — tf32 convert into [cog][chunk][m][k]
// ---------------------------------------------------------------------------
__global__ void prep_w_kernel(const float* __restrict__ cw) {
    const int t = blockIdx.x;           // 0..71
    const int cog = t / KCH;
    const int c = t % KCH;
    const int pos = c >> 2;
    const int ci0 = (c & 3) << 5;
    unsigned int* dst = g_wpre + (size_t)t * 4096;
    for (int e = threadIdx.x; e < 4096; e += blockDim.x) {
        int m = e >> 5, kk = e & 31;
        int co = cog * 128 + m;
        dst[e] = to_tf32(cw[(co * CIN + ci0 + kk) * 9 + pos]);
    }
}

// ---------------------------------------------------------------------------
// Kernel 3: main conv via mma.sync tf32 implicit GEMM (NHWC B-build, float2 frags)
// CTA = (cog, h, b): M=128 co, N=112 pixels, K=1152 in 36 chunks of 32.
// ---------------------------------------------------------------------------
#define SA_BUF   18432u   // 128 rows * 36 floats * 4B
#define SB_BASE  36864u
#define SB_BUF   16128u   // 112 rows * 36 floats * 4B
#define SMEM_TOT 69120u

__device__ __forceinline__ void copyA(uint32_t sbase, int bufsel,
                                      const unsigned int* src, int tid) {
#pragma unroll
    for (int p = 0; p < 4; p++) {
        int ci = tid + p * 256;
        int m = ci >> 3, part = ci & 7;
        uint32_t dst = sbase + bufsel * SA_BUF + (uint32_t)(m * 144 + part * 16);
        cp16(dst, src + ci * 4);
    }
}

// B-build split: LDG phase (into regs) / STS phase (cvt + STS.128)
__device__ __forceinline__ void loadB(const float* __restrict__ stb,
                                      int h, int c, int tid, float4* bv) {
    if (tid >= 224) return;
    const int n = tid >> 1, half = tid & 1;
    const int pos = c >> 2;
    const int ci0 = (c & 3) << 5;
    const int ky = pos / 3, kx = pos % 3;
    const int hrow = h + ky - 1;
    const int wi = n + kx - 1;
    if (hrow >= 0 && hrow < H && wi >= 0 && wi < W) {
        const float4* p = reinterpret_cast<const float4*>(
            stb + ((size_t)hrow * W + wi) * CIN + ci0 + half * 16);
        bv[0] = p[0]; bv[1] = p[1]; bv[2] = p[2]; bv[3] = p[3];
    } else {
        float4 z = make_float4(0.f, 0.f, 0.f, 0.f);
        bv[0] = z; bv[1] = z; bv[2] = z; bv[3] = z;
    }
}

__device__ __forceinline__ void stsB(float* sBbuf, int tid, const float4* bv) {
    if (tid >= 224) return;
    const int n = tid >> 1, half = tid & 1;
    float* dst = sBbuf + n * 36 + half * 16;
#pragma unroll
    for (int q = 0; q < 4; q++) {
        float4 t = bv[q];
        t.x = __uint_as_float(to_tf32(t.x));
        t.y = __uint_as_float(to_tf32(t.y));
        t.z = __uint_as_float(to_tf32(t.z));
        t.w = __uint_as_float(to_tf32(t.w));
        *reinterpret_cast<float4*>(dst + q * 4) = t;
    }
}

__global__ void __launch_bounds__(256) conv_mma_kernel(float* __restrict__ out) {
    extern __shared__ char smem[];
    float* sA = (float*)smem;                  // [2][128][36]
    float* sB = (float*)(smem + SB_BASE);      // [2][112][36]
    const uint32_t sbase = smem_u32(smem);

    const int tid = threadIdx.x;
    const int wid = tid >> 5;
    const int lane = tid & 31;
    const int warp_m = wid & 3;
    const int warp_n = wid >> 2;
    const int tr = lane >> 2;
    const int tc = lane & 3;

    const int cog = blockIdx.x;
    const int h   = blockIdx.y;
    const int b   = blockIdx.z;
    const float* stb = g_st + (size_t)b * HW * CIN;
    const unsigned int* wsrc = g_wpre + (size_t)cog * KCH * 4096;

    float acc[2][7][4];
#pragma unroll
    for (int mt = 0; mt < 2; mt++)
#pragma unroll
        for (int j = 0; j < 7; j++)
#pragma unroll
            for (int q = 0; q < 4; q++) acc[mt][j][q] = 0.f;

    float4 bv[4];
    copyA(sbase, 0, wsrc, tid);
    CP_COMMIT();
    loadB(stb, h, 0, tid, bv);
    CP_WAIT0();
    stsB(sB, tid, bv);
    __syncthreads();

    for (int c = 0; c < KCH; c++) {
        const int buf = c & 1;
        const bool more = (c + 1 < KCH);
        if (more) {
            copyA(sbase, buf ^ 1, wsrc + (size_t)(c + 1) * 4096, tid);
            CP_COMMIT();
            loadB(stb, h, c + 1, tid, bv);
        }
        {
            const float* Ab = sA + buf * (SA_BUF / 4);
            const float* Bb = sB + buf * (SB_BUF / 4);
#pragma unroll
            for (int ks = 0; ks < 4; ks++) {
                // memory positions (2tc, 2tc+1) feed HW k-slots (tc, tc+4)
                unsigned a[2][4];
#pragma unroll
                for (int mt = 0; mt < 2; mt++) {
                    int r0 = warp_m * 32 + mt * 16 + tr;
                    float2 lo = *reinterpret_cast<const float2*>(&Ab[r0 * 36 + ks * 8 + tc * 2]);
                    float2 hi = *reinterpret_cast<const float2*>(&Ab[(r0 + 8) * 36 + ks * 8 + tc * 2]);
                    a[mt][0] = __float_as_uint(lo.x);
                    a[mt][1] = __float_as_uint(hi.x);
                    a[mt][2] = __float_as_uint(lo.y);
                    a[mt][3] = __float_as_uint(hi.y);
                }
                unsigned bf[7][2];
#pragma unroll
                for (int j = 0; j < 7; j++) {
                    int n0 = warp_n * 56 + j * 8 + tr;
                    float2 bb = *reinterpret_cast<const float2*>(&Bb[n0 * 36 + ks * 8 + tc * 2]);
                    bf[j][0] = __float_as_uint(bb.x);
                    bf[j][1] = __float_as_uint(bb.y);
                }
#pragma unroll
                for (int mt = 0; mt < 2; mt++)
#pragma unroll
                    for (int j = 0; j < 7; j++)
                        mma_tf32(acc[mt][j], a[mt], bf[j]);
            }
        }
        if (more) {
            CP_WAIT0();
            stsB(sB + (buf ^ 1) * (SB_BUF / 4), tid, bv);
        }
        __syncthreads();
    }

    // epilogue
#pragma unroll
    for (int mt = 0; mt < 2; mt++) {
        int r = warp_m * 32 + mt * 16 + tr;
        int co = cog * 128 + r;
#pragma unroll
        for (int j = 0; j < 7; j++) {
            int w0 = warp_n * 56 + j * 8 + tc * 2;
            float* op = out + (((size_t)b * COUT + co) * H + h) * W + w0;
            *reinterpret_cast<float2*>(op) = make_float2(acc[mt][j][0], acc[mt][j][1]);
            float* op2 = op + (size_t)8 * HW;   // co + 8
            *reinterpret_cast<float2*>(op2) = make_float2(acc[mt][j][2], acc[mt][j][3]);
        }
    }
}

// ---------------------------------------------------------------------------
extern "C" void kernel_launch(void* const* d_in, const int* in_sizes, int n_in,
                              void* d_out, int out_size) {
    const float* x  = (const float*)d_in[0];   // (8,128,112,112)
    const float* ow = (const float*)d_in[1];   // (18,128,3,3)
    const float* ob = (const float*)d_in[2];   // (18)
    const float* cw = (const float*)d_in[3];   // (256,128,3,3)
    float* out = (float*)d_out;                // (8,256,112,112)

    cudaFuncSetAttribute(conv_mma_kernel,
                         cudaFuncAttributeMaxDynamicSharedMemorySize, SMEM_TOT);

    prep_w_kernel<<<2 * KCH, 256>>>(cw);
    dim3 grid_row(H, BATCH);
    transpose_kernel<<<grid_row, 256>>>(x);
    dim3 grid_off(H / 2, BATCH);
    offset_conv_kernel<<<grid_off, 128>>>(x, ow, ob);
    sample_kernel<<<grid_row, 128>>>();
    dim3 grid_conv(2, H, BATCH);
    conv_mma_kernel<<<grid_conv, 256, SMEM_TOT>>>(out);
}

// round 8
// speedup vs baseline: 1.0853x; 1.0853x over previous
#include <cuda_runtime.h>
#include <math.h>
#include <stdint.h>

#define BATCH 8
#define CIN   128
#define H     112
#define W     112
#define COUT  256
#define OFFC  18
#define HW    (H * W)
#define KCH   36        // k chunks of 32 (1152 total)

// ---------------------------------------------------------------------------
// Scratch (allocation-free rule: __device__ globals)
// ---------------------------------------------------------------------------
__device__ float g_offset[BATCH * OFFC * HW];
__device__ __align__(16) float g_xt[(size_t)BATCH * HW * CIN];   // (B,H,W,C)
__device__ __align__(16) float g_st[(size_t)BATCH * HW * CIN];   // sampled, (B,H,W,C)
// tf32 weights: [cog(2)][chunk(36)][m(128)][k(32)]
__device__ __align__(16) unsigned int g_wpre[2 * KCH * 4096];

// ---------------------------------------------------------------------------
// helpers
// ---------------------------------------------------------------------------
__device__ __forceinline__ uint32_t smem_u32(const void* p) {
    uint32_t a;
    asm("{ .reg .u64 t; cvta.to.shared.u64 t, %1; cvt.u32.u64 %0, t; }" : "=r"(a) : "l"(p));
    return a;
}
__device__ __forceinline__ unsigned int to_tf32(float v) {
    unsigned int t; asm("cvt.rna.tf32.f32 %0, %1;" : "=r"(t) : "f"(v)); return t;
}
__device__ __forceinline__ void cp16(uint32_t dst, const void* src) {
    asm volatile("cp.async.cg.shared.global [%0], [%1], 16;" :: "r"(dst), "l"(src) : "memory");
}
#define CP_COMMIT() asm volatile("cp.async.commit_group;" ::: "memory")
#define CP_WAIT0()  asm volatile("cp.async.wait_group 0;" ::: "memory")

__device__ __forceinline__ void mma_tf32(float* d, const unsigned* a, const unsigned* b) {
    asm volatile(
        "mma.sync.aligned.m16n8k8.row.col.f32.tf32.tf32.f32 "
        "{%0,%1,%2,%3}, {%4,%5,%6,%7}, {%8,%9}, {%0,%1,%2,%3};"
        : "+f"(d[0]), "+f"(d[1]), "+f"(d[2]), "+f"(d[3])
        : "r"(a[0]), "r"(a[1]), "r"(a[2]), "r"(a[3]), "r"(b[0]), "r"(b[1]));
}

// ---------------------------------------------------------------------------
// Kernel 0: transpose x (B,C,H,W) -> g_xt (B,H,W,C)
// ---------------------------------------------------------------------------
__global__ void transpose_kernel(const float* __restrict__ x) {
    __shared__ float tile[CIN * 29];
    const int h = blockIdx.x;
    const int b = blockIdx.y;
    const int tid = threadIdx.x;
    for (int wc = 0; wc < 4; wc++) {
        for (int e = tid; e < CIN * 28; e += 256) {
            int c = e / 28, j = e % 28;
            tile[c * 29 + j] = x[((size_t)(b * CIN + c) * H + h) * W + wc * 28 + j];
        }
        __syncthreads();
        for (int e = tid; e < CIN * 28; e += 256) {
            int j = e >> 7, c = e & 127;
            g_xt[(((size_t)b * H + h) * W + wc * 28 + j) * CIN + c] = tile[c * 29 + j];
        }
        __syncthreads();
    }
}

// ---------------------------------------------------------------------------
// Kernel 1: offset conv — 2 h-rows per block
// ---------------------------------------------------------------------------
#define K1_CK 16
__global__ void offset_conv_kernel(const float* __restrict__ x,
                                   const float* __restrict__ ow,
                                   const float* __restrict__ ob) {
    __shared__ float sW[K1_CK * 9 * OFFC];
    __shared__ float sX[K1_CK * 4 * 114];     // rows h0-1 .. h0+2
    const int h0 = blockIdx.x * 2;
    const int b  = blockIdx.y;
    const int tid = threadIdx.x;
    const int w = tid;

    float acc0[OFFC], acc1[OFFC];
#pragma unroll
    for (int oc = 0; oc < OFFC; oc++) { acc0[oc] = ob[oc]; acc1[oc] = acc0[oc]; }

    for (int c0 = 0; c0 < CIN; c0 += K1_CK) {
        for (int e = tid; e < K1_CK * 4 * 114; e += blockDim.x) {
            int ci = e / (4 * 114), rem = e % (4 * 114);
            int r = rem / 114, j = rem % 114;
            int row = h0 - 1 + r, col = j - 1;
            float v = 0.f;
            if (row >= 0 && row < H && col >= 0 && col < W)
                v = x[((size_t)(b * CIN + c0 + ci) * H + row) * W + col];
            sX[e] = v;
        }
        for (int e = tid; e < K1_CK * 9 * OFFC; e += blockDim.x) {
            int ci = e / (9 * OFFC), rem = e % (9 * OFFC);
            int k = rem / OFFC, oc = rem % OFFC;
            sW[e] = ow[(oc * CIN + c0 + ci) * 9 + k];
        }
        __syncthreads();
        if (w < W) {
            for (int ci = 0; ci < K1_CK; ci++) {
                float xv[4][3];
#pragma unroll
                for (int r = 0; r < 4; r++)
#pragma unroll
                    for (int kx = 0; kx < 3; kx++)
                        xv[r][kx] = sX[(ci * 4 + r) * 114 + w + kx];
#pragma unroll
                for (int k = 0; k < 9; k++) {
                    int ky = k / 3, kx = k % 3;
                    float v0 = xv[ky][kx];
                    float v1 = xv[ky + 1][kx];
                    const float* wp = &sW[(ci * 9 + k) * OFFC];
#pragma unroll
                    for (int oc = 0; oc < OFFC; oc++) {
                        float wv = wp[oc];
                        acc0[oc] += v0 * wv;
                        acc1[oc] += v1 * wv;
                    }
                }
            }
        }
        __syncthreads();
    }
    if (w < W) {
#pragma unroll
        for (int oc = 0; oc < OFFC; oc++) {
            g_offset[((size_t)(b * OFFC + oc) * H + h0)     * W + w] = acc0[oc];
            g_offset[((size_t)(b * OFFC + oc) * H + h0 + 1) * W + w] = acc1[oc];
        }
    }
}

// ---------------------------------------------------------------------------
// Kernel 2: sampling — corner table in smem, channel-vectorized gathers (NHWC)
// ---------------------------------------------------------------------------
__global__ void __launch_bounds__(128) sample_kernel() {
    __shared__ float2 sTab[112 * 36];     // {idx-as-float, weight}
    const int h = blockIdx.x;
    const int b = blockIdx.y;
    const int tid = threadIdx.x;
    const int wid = tid >> 5;
    const int lane = tid & 31;

    if (tid < W) {
        const int w = tid;
        const float* offp = g_offset + (size_t)b * OFFC * HW + h * W + w;
#pragma unroll
        for (int p = 0; p < 9; p++) {
            int ky = p / 3, kx = p % 3;
            float offY = offp[(size_t)p * HW];
            float offX = offp[(size_t)(9 + p) * HW];
            float sy = (float)(h + ky - 1) + offY;
            float sx = (float)(w + kx - 1) + offX;
            float fy0 = floorf(sy), fx0 = floorf(sx);
            int y0 = (int)fy0, x0 = (int)fx0;
            float wy = sy - fy0, wx = sx - fx0;
#pragma unroll
            for (int q = 0; q < 4; q++) {
                int yi = y0 + (q >> 1), xi = x0 + (q & 1);
                float wgt = ((q >> 1) ? wy : 1.f - wy) * ((q & 1) ? wx : 1.f - wx);
                bool valid = (yi >= 0) & (yi < H) & (xi >= 0) & (xi < W);
                int yc = min(max(yi, 0), H - 1);
                int xc = min(max(xi, 0), W - 1);
                sTab[w * 36 + p * 4 + q] =
                    make_float2(__int_as_float(yc * W + xc), valid ? wgt : 0.f);
            }
        }
    }
    __syncthreads();

    const float* xtb = g_xt + (size_t)b * HW * CIN;
    float* stb = g_st + (size_t)b * HW * CIN;
    for (int w = wid; w < W; w += 4) {
        float4 acc = make_float4(0.f, 0.f, 0.f, 0.f);
        const float2* tab = &sTab[w * 36];
#pragma unroll 9
        for (int q = 0; q < 36; q++) {
            float2 t = tab[q];
            int pix = __float_as_int(t.x);
            float wt = t.y;
            float4 v = *reinterpret_cast<const float4*>(xtb + (size_t)pix * CIN + lane * 4);
            acc.x += wt * v.x; acc.y += wt * v.y;
            acc.z += wt * v.z; acc.w += wt * v.w;
        }
        *reinterpret_cast<float4*>(stb + (size_t)(h * W + w) * CIN + lane * 4) = acc;
    }
}

// ---------------------------------------------------------------------------
// Kernel 2.5: weight prep — tf32 convert into [cog][chunk][m][k]
// ---------------------------------------------------------------------------
__global__ void prep_w_kernel(const float* __restrict__ cw) {
    const int t = blockIdx.x;           // 0..71
    const int cog = t / KCH;
    const int c = t % KCH;
    const int pos = c >> 2;
    const int ci0 = (c & 3) << 5;
    unsigned int* dst = g_wpre + (size_t)t * 4096;
    for (int e = threadIdx.x; e < 4096; e += blockDim.x) {
        int m = e >> 5, kk = e & 31;
        int co = cog * 128 + m;
        dst[e] = to_tf32(cw[(co * CIN + ci0 + kk) * 9 + pos]);
    }
}

// ---------------------------------------------------------------------------
// Kernel 3: main conv via mma.sync tf32 implicit GEMM.
// Stride-40 smem (8-bank row step -> conflict-free LDS.64 fragments).
// B rows XOR-swizzled by 2*(n&3): STS.128 conflict-free; loads fold the
// swizzle into tcx = tc ^ (tr&3).
// ---------------------------------------------------------------------------
#define SA_STR   40
#define SB_STR   40
#define SA_BUF   20480u   // 128 * 40 * 4B
#define SB_BASE  40960u
#define SB_BUF   17920u   // 112 * 40 * 4B
#define SMEM_TOT 76800u

__device__ __forceinline__ void copyA(uint32_t sbase, int bufsel,
                                      const unsigned int* src, int tid) {
#pragma unroll
    for (int p = 0; p < 4; p++) {
        int ci = tid + p * 256;
        int m = ci >> 3, part = ci & 7;
        uint32_t dst = sbase + bufsel * SA_BUF + (uint32_t)(m * (SA_STR * 4) + part * 16);
        cp16(dst, src + ci * 4);
    }
}

__device__ __forceinline__ void loadB(const float* __restrict__ stb,
                                      int h, int c, int tid, float4* bv) {
    if (tid >= 224) return;
    const int n = tid >> 1, half = tid & 1;
    const int pos = c >> 2;
    const int ci0 = (c & 3) << 5;
    const int ky = pos / 3, kx = pos % 3;
    const int hrow = h + ky - 1;
    const int wi = n + kx - 1;
    if (hrow >= 0 && hrow < H && wi >= 0 && wi < W) {
        const float4* p = reinterpret_cast<const float4*>(
            stb + ((size_t)hrow * W + wi) * CIN + ci0 + half * 16);
        bv[0] = p[0]; bv[1] = p[1]; bv[2] = p[2]; bv[3] = p[3];
    } else {
        float4 z = make_float4(0.f, 0.f, 0.f, 0.f);
        bv[0] = z; bv[1] = z; bv[2] = z; bv[3] = z;
    }
}

__device__ __forceinline__ void stsB(float* sBbuf, int tid, const float4* bv) {
    if (tid >= 224) return;
    const int n = tid >> 1, half = tid & 1;
    const int qsw = (n >> 1) & 1;       // XOR-by-4 part of swizzle
    const int psw = n & 1;              // XOR-by-2 part (pair swap in block)
    float* dst = sBbuf + n * SB_STR + half * 16;
#pragma unroll
    for (int q = 0; q < 4; q++) {
        float4 t = bv[q];
        t.x = __uint_as_float(to_tf32(t.x));
        t.y = __uint_as_float(to_tf32(t.y));
        t.z = __uint_as_float(to_tf32(t.z));
        t.w = __uint_as_float(to_tf32(t.w));
        if (psw) t = make_float4(t.z, t.w, t.x, t.y);
        *reinterpret_cast<float4*>(dst + (q ^ qsw) * 4) = t;
    }
}

__global__ void __launch_bounds__(256) conv_mma_kernel(float* __restrict__ out) {
    extern __shared__ char smem[];
    float* sA = (float*)smem;                  // [2][128][40]
    float* sB = (float*)(smem + SB_BASE);      // [2][112][40] (swizzled)
    const uint32_t sbase = smem_u32(smem);

    const int tid = threadIdx.x;
    const int wid = tid >> 5;
    const int lane = tid & 31;
    const int warp_m = wid & 3;
    const int warp_n = wid >> 2;
    const int tr = lane >> 2;
    const int tc = lane & 3;
    const int tcx = tc ^ (tr & 3);      // B-side swizzled column

    const int cog = blockIdx.x;
    const int h   = blockIdx.y;
    const int b   = blockIdx.z;
    const float* stb = g_st + (size_t)b * HW * CIN;
    const unsigned int* wsrc = g_wpre + (size_t)cog * KCH * 4096;

    float acc[2][7][4];
#pragma unroll
    for (int mt = 0; mt < 2; mt++)
#pragma unroll
        for (int j = 0; j < 7; j++)
#pragma unroll
            for (int q = 0; q < 4; q++) acc[mt][j][q] = 0.f;

    float4 bv[4];
    copyA(sbase, 0, wsrc, tid);
    CP_COMMIT();
    loadB(stb, h, 0, tid, bv);
    CP_WAIT0();
    stsB(sB, tid, bv);
    __syncthreads();

    for (int c = 0; c < KCH; c++) {
        const int buf = c & 1;
        const bool more = (c + 1 < KCH);
        if (more) {
            copyA(sbase, buf ^ 1, wsrc + (size_t)(c + 1) * 4096, tid);
            CP_COMMIT();
            loadB(stb, h, c + 1, tid, bv);
        }
        {
            const float* Ab = sA + buf * (SA_BUF / 4);
            const float* Bb = sB + buf * (SB_BUF / 4);
#pragma unroll
            for (int ks = 0; ks < 4; ks++) {
                // memory k-positions (2tc, 2tc+1) feed HW k-slots (tc, tc+4)
                unsigned a[2][4];
#pragma unroll
                for (int mt = 0; mt < 2; mt++) {
                    int r0 = warp_m * 32 + mt * 16 + tr;
                    float2 lo = *reinterpret_cast<const float2*>(&Ab[r0 * SA_STR + ks * 8 + tc * 2]);
                    float2 hi = *reinterpret_cast<const float2*>(&Ab[(r0 + 8) * SA_STR + ks * 8 + tc * 2]);
                    a[mt][0] = __float_as_uint(lo.x);
                    a[mt][1] = __float_as_uint(hi.x);
                    a[mt][2] = __float_as_uint(lo.y);
                    a[mt][3] = __float_as_uint(hi.y);
                }
                unsigned bf[7][2];
#pragma unroll
                for (int j = 0; j < 7; j++) {
                    int n0 = warp_n * 56 + j * 8 + tr;
                    float2 bb = *reinterpret_cast<const float2*>(&Bb[n0 * SB_STR + ks * 8 + tcx * 2]);
                    bf[j][0] = __float_as_uint(bb.x);
                    bf[j][1] = __float_as_uint(bb.y);
                }
#pragma unroll
                for (int mt = 0; mt < 2; mt++)
#pragma unroll
                    for (int j = 0; j < 7; j++)
                        mma_tf32(acc[mt][j], a[mt], bf[j]);
            }
        }
        if (more) {
            CP_WAIT0();
            stsB(sB + (buf ^ 1) * (SB_BUF / 4), tid, bv);
        }
        __syncthreads();
    }

    // epilogue
#pragma unroll
    for (int mt = 0; mt < 2; mt++) {
        int r = warp_m * 32 + mt * 16 + tr;
        int co = cog * 128 + r;
#pragma unroll
        for (int j = 0; j < 7; j++) {
            int w0 = warp_n * 56 + j * 8 + tc * 2;
            float* op = out + (((size_t)b * COUT + co) * H + h) * W + w0;
            *reinterpret_cast<float2*>(op) = make_float2(acc[mt][j][0], acc[mt][j][1]);
            float* op2 = op + (size_t)8 * HW;   // co + 8
            *reinterpret_cast<float2*>(op2) = make_float2(acc[mt][j][2], acc[mt][j][3]);
        }
    }
}

// ---------------------------------------------------------------------------
extern "C" void kernel_launch(void* const* d_in, const int* in_sizes, int n_in,
                              void* d_out, int out_size) {
    const float* x  = (const float*)d_in[0];   // (8,128,112,112)
    const float* ow = (const float*)d_in[1];   // (18,128,3,3)
    const float* ob = (const float*)d_in[2];   // (18)
    const float* cw = (const float*)d_in[3];   // (256,128,3,3)
    float* out = (float*)d_out;                // (8,256,112,112)

    cudaFuncSetAttribute(conv_mma_kernel,
                         cudaFuncAttributeMaxDynamicSharedMemorySize, SMEM_TOT);

    prep_w_kernel<<<2 * KCH, 256>>>(cw);
    dim3 grid_row(H, BATCH);
    transpose_kernel<<<grid_row, 256>>>(x);
    dim3 grid_off(H / 2, BATCH);
    offset_conv_kernel<<<grid_off, 128>>>(x, ow, ob);
    sample_kernel<<<grid_row, 128>>>();
    dim3 grid_conv(2, H, BATCH);
    conv_mma_kernel<<<grid_conv, 256, SMEM_TOT>>>(out);
}

// round 9
// speedup vs baseline: 1.1281x; 1.0395x over previous
#include <cuda_runtime.h>
#include <math.h>
#include <stdint.h>

#define BATCH 8
#define CIN   128
#define H     112
#define W     112
#define COUT  256
#define OFFC  18
#define HW    (H * W)
#define KCH   36        // k chunks of 32 (1152 total)

// ---------------------------------------------------------------------------
// Scratch (allocation-free rule: __device__ globals)
// ---------------------------------------------------------------------------
__device__ float g_offset[BATCH * OFFC * HW];
__device__ __align__(16) float g_xt[(size_t)BATCH * HW * CIN];   // (B,H,W,C)
__device__ __align__(16) float g_st[(size_t)BATCH * HW * CIN];   // sampled, (B,H,W,C)
// tf32 weights: [chunk(36)][m(256)][k(32)]
__device__ __align__(16) unsigned int g_wpre[KCH * 256 * 32];

// ---------------------------------------------------------------------------
// helpers
// ---------------------------------------------------------------------------
__device__ __forceinline__ uint32_t smem_u32(const void* p) {
    uint32_t a;
    asm("{ .reg .u64 t; cvta.to.shared.u64 t, %1; cvt.u32.u64 %0, t; }" : "=r"(a) : "l"(p));
    return a;
}
__device__ __forceinline__ unsigned int to_tf32(float v) {
    unsigned int t; asm("cvt.rna.tf32.f32 %0, %1;" : "=r"(t) : "f"(v)); return t;
}
__device__ __forceinline__ void cp16(uint32_t dst, const void* src) {
    asm volatile("cp.async.cg.shared.global [%0], [%1], 16;" :: "r"(dst), "l"(src) : "memory");
}
#define CP_COMMIT() asm volatile("cp.async.commit_group;" ::: "memory")
#define CP_WAIT0()  asm volatile("cp.async.wait_group 0;" ::: "memory")

__device__ __forceinline__ void mma_tf32(float* d, const unsigned* a, const unsigned* b) {
    asm volatile(
        "mma.sync.aligned.m16n8k8.row.col.f32.tf32.tf32.f32 "
        "{%0,%1,%2,%3}, {%4,%5,%6,%7}, {%8,%9}, {%0,%1,%2,%3};"
        : "+f"(d[0]), "+f"(d[1]), "+f"(d[2]), "+f"(d[3])
        : "r"(a[0]), "r"(a[1]), "r"(a[2]), "r"(a[3]), "r"(b[0]), "r"(b[1]));
}

// ---------------------------------------------------------------------------
// Kernel 0: transpose x (B,C,H,W) -> g_xt (B,H,W,C)
// ---------------------------------------------------------------------------
__global__ void transpose_kernel(const float* __restrict__ x) {
    __shared__ float tile[CIN * 29];
    const int h = blockIdx.x;
    const int b = blockIdx.y;
    const int tid = threadIdx.x;
    for (int wc = 0; wc < 4; wc++) {
        for (int e = tid; e < CIN * 28; e += 256) {
            int c = e / 28, j = e % 28;
            tile[c * 29 + j] = x[((size_t)(b * CIN + c) * H + h) * W + wc * 28 + j];
        }
        __syncthreads();
        for (int e = tid; e < CIN * 28; e += 256) {
            int j = e >> 7, c = e & 127;
            g_xt[(((size_t)b * H + h) * W + wc * 28 + j) * CIN + c] = tile[c * 29 + j];
        }
        __syncthreads();
    }
}

// ---------------------------------------------------------------------------
// Kernel 1: offset conv — 4 h-rows per block (weight LDS amortized x4)
// ---------------------------------------------------------------------------
#define K1_CK 8
__global__ void offset_conv_kernel(const float* __restrict__ x,
                                   const float* __restrict__ ow,
                                   const float* __restrict__ ob) {
    __shared__ float sW[K1_CK * 9 * OFFC];
    __shared__ float sX[K1_CK * 6 * 114];     // rows h0-1 .. h0+4
    const int h0 = blockIdx.x * 4;
    const int b  = blockIdx.y;
    const int tid = threadIdx.x;
    const int w = tid;

    float acc[4][OFFC];
#pragma unroll
    for (int oc = 0; oc < OFFC; oc++) {
        float bv = ob[oc];
#pragma unroll
        for (int r = 0; r < 4; r++) acc[r][oc] = bv;
    }

    for (int c0 = 0; c0 < CIN; c0 += K1_CK) {
        for (int e = tid; e < K1_CK * 6 * 114; e += blockDim.x) {
            int ci = e / (6 * 114), rem = e % (6 * 114);
            int r = rem / 114, j = rem % 114;
            int row = h0 - 1 + r, col = j - 1;
            float v = 0.f;
            if (row >= 0 && row < H && col >= 0 && col < W)
                v = x[((size_t)(b * CIN + c0 + ci) * H + row) * W + col];
            sX[e] = v;
        }
        for (int e = tid; e < K1_CK * 9 * OFFC; e += blockDim.x) {
            int ci = e / (9 * OFFC), rem = e % (9 * OFFC);
            int k = rem / OFFC, oc = rem % OFFC;
            sW[e] = ow[(oc * CIN + c0 + ci) * 9 + k];
        }
        __syncthreads();
        if (w < W) {
            for (int ci = 0; ci < K1_CK; ci++) {
                float xv[6][3];
#pragma unroll
                for (int r = 0; r < 6; r++)
#pragma unroll
                    for (int kx = 0; kx < 3; kx++)
                        xv[r][kx] = sX[(ci * 6 + r) * 114 + w + kx];
#pragma unroll
                for (int k = 0; k < 9; k++) {
                    int ky = k / 3, kx = k % 3;
                    const float* wp = &sW[(ci * 9 + k) * OFFC];
#pragma unroll
                    for (int oc = 0; oc < OFFC; oc++) {
                        float wv = wp[oc];
                        acc[0][oc] += xv[ky][kx] * wv;
                        acc[1][oc] += xv[ky + 1][kx] * wv;
                        acc[2][oc] += xv[ky + 2][kx] * wv;
                        acc[3][oc] += xv[ky + 3][kx] * wv;
                    }
                }
            }
        }
        __syncthreads();
    }
    if (w < W) {
#pragma unroll
        for (int r = 0; r < 4; r++)
#pragma unroll
            for (int oc = 0; oc < OFFC; oc++)
                g_offset[((size_t)(b * OFFC + oc) * H + h0 + r) * W + w] = acc[r][oc];
    }
}

// ---------------------------------------------------------------------------
// Kernel 2: sampling — corner table in smem, channel-vectorized gathers (NHWC)
// ---------------------------------------------------------------------------
__global__ void __launch_bounds__(128) sample_kernel() {
    __shared__ float2 sTab[112 * 36];     // {idx-as-float, weight}
    const int h = blockIdx.x;
    const int b = blockIdx.y;
    const int tid = threadIdx.x;
    const int wid = tid >> 5;
    const int lane = tid & 31;

    if (tid < W) {
        const int w = tid;
        const float* offp = g_offset + (size_t)b * OFFC * HW + h * W + w;
#pragma unroll
        for (int p = 0; p < 9; p++) {
            int ky = p / 3, kx = p % 3;
            float offY = offp[(size_t)p * HW];
            float offX = offp[(size_t)(9 + p) * HW];
            float sy = (float)(h + ky - 1) + offY;
            float sx = (float)(w + kx - 1) + offX;
            float fy0 = floorf(sy), fx0 = floorf(sx);
            int y0 = (int)fy0, x0 = (int)fx0;
            float wy = sy - fy0, wx = sx - fx0;
#pragma unroll
            for (int q = 0; q < 4; q++) {
                int yi = y0 + (q >> 1), xi = x0 + (q & 1);
                float wgt = ((q >> 1) ? wy : 1.f - wy) * ((q & 1) ? wx : 1.f - wx);
                bool valid = (yi >= 0) & (yi < H) & (xi >= 0) & (xi < W);
                int yc = min(max(yi, 0), H - 1);
                int xc = min(max(xi, 0), W - 1);
                sTab[w * 36 + p * 4 + q] =
                    make_float2(__int_as_float(yc * W + xc), valid ? wgt : 0.f);
            }
        }
    }
    __syncthreads();

    const float* xtb = g_xt + (size_t)b * HW * CIN;
    float* stb = g_st + (size_t)b * HW * CIN;
    for (int w = wid; w < W; w += 4) {
        float4 acc = make_float4(0.f, 0.f, 0.f, 0.f);
        const float2* tab = &sTab[w * 36];
#pragma unroll 9
        for (int q = 0; q < 36; q++) {
            float2 t = tab[q];
            int pix = __float_as_int(t.x);
            float wt = t.y;
            float4 v = *reinterpret_cast<const float4*>(xtb + (size_t)pix * CIN + lane * 4);
            acc.x += wt * v.x; acc.y += wt * v.y;
            acc.z += wt * v.z; acc.w += wt * v.w;
        }
        *reinterpret_cast<float4*>(stb + (size_t)(h * W + w) * CIN + lane * 4) = acc;
    }
}

// ---------------------------------------------------------------------------
// Kernel 2.5: weight prep — tf32 convert into [chunk][m=256][k=32]
// chunk c: pos = c/4 (ky*3+kx), ci0 = (c%4)*32
// ---------------------------------------------------------------------------
__global__ void prep_w_kernel(const float* __restrict__ cw) {
    const int c = blockIdx.x;           // 0..35
    const int pos = c >> 2;
    const int ci0 = (c & 3) << 5;
    unsigned int* dst = g_wpre + (size_t)c * 8192;
    for (int e = threadIdx.x; e < 8192; e += blockDim.x) {
        int co = e >> 5, kk = e & 31;
        dst[e] = to_tf32(cw[(co * CIN + ci0 + kk) * 9 + pos]);
    }
}

// ---------------------------------------------------------------------------
// Kernel 3: main conv via mma.sync tf32 implicit GEMM, M=256 per CTA.
// CTA = (h, b): M=256 co (both halves), N=112 pixels, K=1152 in 36 chunks.
// 8 warps = 4(M:32-row groups, x2 for upper 128) x 2(N:56): warp tile 64co x 56w,
// 4x7 m16n8k8 MMAs per k8. Stride-40 smem, B XOR-swizzle (as R7).
// ---------------------------------------------------------------------------
#define SA_STR   40
#define SB_STR   40
#define SA_BUF   40960u   // 256 * 40 * 4B
#define SB_BASE  81920u
#define SB_BUF   17920u   // 112 * 40 * 4B
#define SMEM_TOT 117760u

__device__ __forceinline__ void copyA(uint32_t sbase, int bufsel,
                                      const unsigned int* src, int tid) {
#pragma unroll
    for (int p = 0; p < 8; p++) {
        int ci = tid + p * 256;             // 2048 16B-chunks (256 rows x 8)
        int m = ci >> 3, part = ci & 7;
        uint32_t dst = sbase + bufsel * SA_BUF + (uint32_t)(m * (SA_STR * 4) + part * 16);
        cp16(dst, src + ci * 4);
    }
}

__device__ __forceinline__ void loadB(const float* __restrict__ stb,
                                      int h, int c, int tid, float4* bv) {
    if (tid >= 224) return;
    const int n = tid >> 1, half = tid & 1;
    const int pos = c >> 2;
    const int ci0 = (c & 3) << 5;
    const int ky = pos / 3, kx = pos % 3;
    const int hrow = h + ky - 1;
    const int wi = n + kx - 1;
    if (hrow >= 0 && hrow < H && wi >= 0 && wi < W) {
        const float4* p = reinterpret_cast<const float4*>(
            stb + ((size_t)hrow * W + wi) * CIN + ci0 + half * 16);
        bv[0] = p[0]; bv[1] = p[1]; bv[2] = p[2]; bv[3] = p[3];
    } else {
        float4 z = make_float4(0.f, 0.f, 0.f, 0.f);
        bv[0] = z; bv[1] = z; bv[2] = z; bv[3] = z;
    }
}

__device__ __forceinline__ void stsB(float* sBbuf, int tid, const float4* bv) {
    if (tid >= 224) return;
    const int n = tid >> 1, half = tid & 1;
    const int qsw = (n >> 1) & 1;
    const int psw = n & 1;
    float* dst = sBbuf + n * SB_STR + half * 16;
#pragma unroll
    for (int q = 0; q < 4; q++) {
        float4 t = bv[q];
        t.x = __uint_as_float(to_tf32(t.x));
        t.y = __uint_as_float(to_tf32(t.y));
        t.z = __uint_as_float(to_tf32(t.z));
        t.w = __uint_as_float(to_tf32(t.w));
        if (psw) t = make_float4(t.z, t.w, t.x, t.y);
        *reinterpret_cast<float4*>(dst + (q ^ qsw) * 4) = t;
    }
}

__global__ void __launch_bounds__(256) conv_mma_kernel(float* __restrict__ out) {
    extern __shared__ char smem[];
    float* sA = (float*)smem;                  // [2][256][40]
    float* sB = (float*)(smem + SB_BASE);      // [2][112][40] (swizzled)
    const uint32_t sbase = smem_u32(smem);

    const int tid = threadIdx.x;
    const int wid = tid >> 5;
    const int lane = tid & 31;
    const int warp_m = wid & 3;
    const int warp_n = wid >> 2;
    const int tr = lane >> 2;
    const int tc = lane & 3;
    const int tcx = tc ^ (tr & 3);

    const int h = blockIdx.x;
    const int b = blockIdx.y;
    const float* stb = g_st + (size_t)b * HW * CIN;

    float acc[4][7][4];
#pragma unroll
    for (int mt = 0; mt < 4; mt++)
#pragma unroll
        for (int j = 0; j < 7; j++)
#pragma unroll
            for (int q = 0; q < 4; q++) acc[mt][j][q] = 0.f;

    float4 bv[4];
    copyA(sbase, 0, g_wpre, tid);
    CP_COMMIT();
    loadB(stb, h, 0, tid, bv);
    CP_WAIT0();
    stsB(sB, tid, bv);
    __syncthreads();

    for (int c = 0; c < KCH; c++) {
        const int buf = c & 1;
        const bool more = (c + 1 < KCH);
        if (more) {
            copyA(sbase, buf ^ 1, g_wpre + (size_t)(c + 1) * 8192, tid);
            CP_COMMIT();
            loadB(stb, h, c + 1, tid, bv);
        }
        {
            const float* Ab = sA + buf * (SA_BUF / 4);
            const float* Bb = sB + buf * (SB_BUF / 4);
#pragma unroll
            for (int ks = 0; ks < 4; ks++) {
                // memory k-positions (2tc, 2tc+1) feed HW k-slots (tc, tc+4)
                unsigned a[4][4];
#pragma unroll
                for (int mt = 0; mt < 4; mt++) {
                    int r0 = warp_m * 32 + (mt & 1) * 16 + (mt >> 1) * 128 + tr;
                    float2 lo = *reinterpret_cast<const float2*>(&Ab[r0 * SA_STR + ks * 8 + tc * 2]);
                    float2 hi = *reinterpret_cast<const float2*>(&Ab[(r0 + 8) * SA_STR + ks * 8 + tc * 2]);
                    a[mt][0] = __float_as_uint(lo.x);
                    a[mt][1] = __float_as_uint(hi.x);
                    a[mt][2] = __float_as_uint(lo.y);
                    a[mt][3] = __float_as_uint(hi.y);
                }
                unsigned bf[7][2];
#pragma unroll
                for (int j = 0; j < 7; j++) {
                    int n0 = warp_n * 56 + j * 8 + tr;
                    float2 bb = *reinterpret_cast<const float2*>(&Bb[n0 * SB_STR + ks * 8 + tcx * 2]);
                    bf[j][0] = __float_as_uint(bb.x);
                    bf[j][1] = __float_as_uint(bb.y);
                }
#pragma unroll
                for (int mt = 0; mt < 4; mt++)
#pragma unroll
                    for (int j = 0; j < 7; j++)
                        mma_tf32(acc[mt][j], a[mt], bf[j]);
            }
        }
        if (more) {
            CP_WAIT0();
            stsB(sB + (buf ^ 1) * (SB_BUF / 4), tid, bv);
        }
        __syncthreads();
    }

    // epilogue
#pragma unroll
    for (int mt = 0; mt < 4; mt++) {
        int co = warp_m * 32 + (mt & 1) * 16 + (mt >> 1) * 128 + tr;
#pragma unroll
        for (int j = 0; j < 7; j++) {
            int w0 = warp_n * 56 + j * 8 + tc * 2;
            float* op = out + (((size_t)b * COUT + co) * H + h) * W + w0;
            *reinterpret_cast<float2*>(op) = make_float2(acc[mt][j][0], acc[mt][j][1]);
            float* op2 = op + (size_t)8 * HW;   // co + 8
            *reinterpret_cast<float2*>(op2) = make_float2(acc[mt][j][2], acc[mt][j][3]);
        }
    }
}

// ---------------------------------------------------------------------------
extern "C" void kernel_launch(void* const* d_in, const int* in_sizes, int n_in,
                              void* d_out, int out_size) {
    const float* x  = (const float*)d_in[0];   // (8,128,112,112)
    const float* ow = (const float*)d_in[1];   // (18,128,3,3)
    const float* ob = (const float*)d_in[2];   // (18)
    const float* cw = (const float*)d_in[3];   // (256,128,3,3)
    float* out = (float*)d_out;                // (8,256,112,112)

    cudaFuncSetAttribute(conv_mma_kernel,
                         cudaFuncAttributeMaxDynamicSharedMemorySize, SMEM_TOT);

    prep_w_kernel<<<KCH, 256>>>(cw);
    dim3 grid_row(H, BATCH);
    transpose_kernel<<<grid_row, 256>>>(x);
    dim3 grid_off(H / 4, BATCH);
    offset_conv_kernel<<<grid_off, 128>>>(x, ow, ob);
    sample_kernel<<<grid_row, 128>>>();
    dim3 grid_conv(H, BATCH);
    conv_mma_kernel<<<grid_conv, 256, SMEM_TOT>>>(out);
}